// round 1
// baseline (speedup 1.0000x reference)
#include <cuda_runtime.h>
#include <cstdint>
#include <cstddef>

#define T_DIM  32
#define K2     512
#define KD     262144           // 1*64*4096 fan-in
#define THRESH 0.2f

#define NSPLIT 512              // K splits
#define KC     (KD / NSPLIT)    // 512 k per block
#define KS     16               // k slab staged in smem
#define NSLAB  (KC / KS)        // 32
#define OTILE  256              // o rows per block (2 o-blocks)
#define WST    260              // padded smem stride for w tile [KS][OTILE]
#define RST    36               // padded smem stride for rec tile [KS][32]

// scratch (device globals: no allocations allowed)
__device__ float g_partial[(size_t)NSPLIT * K2 * T_DIM];  // [sp][o][t], 32 MB
__device__ float g_dot[T_DIM * K2];                       // [t][o]

__device__ __forceinline__ void fma2(unsigned long long& d,
                                     unsigned long long a,
                                     unsigned long long b) {
    asm("fma.rn.f32x2 %0, %1, %2, %0;" : "+l"(d) : "l"(a), "l"(b));
}
__device__ __forceinline__ unsigned long long dup2(float w) {
    unsigned long long r;
    asm("mov.b64 %0, {%1, %1};" : "=l"(r) : "f"(w));
    return r;
}

// ---------------------------------------------------------------------------
// GEMM: partial[sp][o][t] = sum_{k in split sp} rec[t][k] * w[o][k]
// block: 128 threads, C-tile 256 o x 32 t, per-thread 8 o x 8 t (f32x2 on t)
// ---------------------------------------------------------------------------
__global__ void __launch_bounds__(128) gemm_kernel(const float* __restrict__ rec,
                                                   const float* __restrict__ wgt)
{
    __shared__ float ws[KS * WST];   // [kk][o] transposed w tile
    __shared__ float rs[KS * RST];   // [kk][t] transposed rec tile

    const int tid   = threadIdx.x;
    const int ob    = blockIdx.x;            // 0..1
    const int sp    = blockIdx.y;            // 0..NSPLIT-1
    const int og    = tid >> 2;              // 0..31  (o-group, mixed in warp)
    const int tg    = tid & 3;               // 0..3   (t-group)
    const int t0    = tg * 8;
    const int obase = ob * OTILE;
    const int kbase = sp * KC;

    unsigned long long acc[32];              // [oi][tpair]
#pragma unroll
    for (int i = 0; i < 32; i++) acc[i] = 0ULL;

    for (int slab = 0; slab < NSLAB; slab++) {
        const int kb = kbase + slab * KS;

        // stage w: 256 rows x 16 k, float4 loads, transposed store
#pragma unroll
        for (int i = 0; i < 8; i++) {
            int lin  = i * 128 + tid;        // 0..1023
            int orow = lin >> 2;
            int quad = lin & 3;
            const float4 v = *reinterpret_cast<const float4*>(
                wgt + (size_t)(obase + orow) * KD + kb + quad * 4);
            ws[(quad * 4 + 0) * WST + orow] = v.x;
            ws[(quad * 4 + 1) * WST + orow] = v.y;
            ws[(quad * 4 + 2) * WST + orow] = v.z;
            ws[(quad * 4 + 3) * WST + orow] = v.w;
        }
        // stage rec: 32 t x 16 k
#pragma unroll
        for (int i = 0; i < 4; i++) {
            int lin = i * 128 + tid;         // 0..511
            int tt  = lin >> 4;
            int kk  = lin & 15;
            rs[kk * RST + tt] = rec[(size_t)tt * KD + kb + kk];
        }
        __syncthreads();

#pragma unroll
        for (int kk = 0; kk < KS; kk++) {
            const float* wrow = ws + kk * WST + og * 8;
            const float4 wa = *reinterpret_cast<const float4*>(wrow);
            const float4 wb = *reinterpret_cast<const float4*>(wrow + 4);
            const float* rrow = rs + kk * RST + t0;
            const ulonglong2 ra = *reinterpret_cast<const ulonglong2*>(rrow);
            const ulonglong2 rb = *reinterpret_cast<const ulonglong2*>(rrow + 4);
            const unsigned long long r0 = ra.x, r1 = ra.y, r2 = rb.x, r3 = rb.y;

#define COL_STEP(OI, WV)                                                \
            {   unsigned long long wd = dup2(WV);                        \
                fma2(acc[(OI)*4+0], wd, r0);                             \
                fma2(acc[(OI)*4+1], wd, r1);                             \
                fma2(acc[(OI)*4+2], wd, r2);                             \
                fma2(acc[(OI)*4+3], wd, r3); }
            COL_STEP(0, wa.x) COL_STEP(1, wa.y) COL_STEP(2, wa.z) COL_STEP(3, wa.w)
            COL_STEP(4, wb.x) COL_STEP(5, wb.y) COL_STEP(6, wb.z) COL_STEP(7, wb.w)
#undef COL_STEP
        }
        __syncthreads();
    }

    // write partials: [sp][o][t]
#pragma unroll
    for (int oi = 0; oi < 8; oi++) {
        const int o = obase + og * 8 + oi;
        float* dst = g_partial + ((size_t)sp * K2 + o) * T_DIM + t0;
#pragma unroll
        for (int j = 0; j < 4; j++) {
            unsigned long long a = acc[oi * 4 + j];
            float2 v;
            v.x = __uint_as_float((unsigned)(a & 0xffffffffULL));
            v.y = __uint_as_float((unsigned)(a >> 32));
            *reinterpret_cast<float2*>(dst + 2 * j) = v;
        }
    }
}

// ---------------------------------------------------------------------------
// deterministic split-K reduction: g_dot[t][o] = sum_sp partial[sp][o][t]
// ---------------------------------------------------------------------------
__global__ void __launch_bounds__(256) reduce_kernel()
{
    const int o   = blockIdx.x;       // 0..511
    const int tid = threadIdx.x;      // 256
    const int t   = tid & 31;
    const int p   = tid >> 5;         // 0..7

    float s = 0.0f;
    const int per = NSPLIT / 8;       // 64
    for (int i = 0; i < per; i++) {
        const int sp = p * per + i;
        s += g_partial[((size_t)sp * K2 + o) * T_DIM + t];
    }
    __shared__ float red[8][32];
    red[p][t] = s;
    __syncthreads();
    if (p == 0) {
        float v = red[0][t];
#pragma unroll
        for (int q = 1; q < 8; q++) v += red[q][t];
        g_dot[t * K2 + o] = v;
    }
}

// ---------------------------------------------------------------------------
// post: threshold -> spikes -> first-spike value -> global v -> totals ->
// 8-round first-index argmax k-WTA -> binary output
// single block, 512 threads (one per feature)
// ---------------------------------------------------------------------------
__global__ void __launch_bounds__(512) post_kernel(float* __restrict__ outp)
{
    const int o = threadIdx.x;        // feature

    unsigned mask = 0;
    int cnt = 0;
#pragma unroll
    for (int t = 0; t < T_DIM; t++) {
        const float v = g_dot[t * K2 + o];
        if (v >= THRESH) { cnt++; mask |= (1u << t); }
    }
    int first = T_DIM - cnt;                       // clip to [0, T-1]
    if (first > T_DIM - 1) first = T_DIM - 1;
    const float fv    = g_dot[first * K2 + o];
    const float value = (fv < THRESH) ? 0.0f : fv; // pot at first-spike index
    const float cand  = (cnt > 0) ? value : 0.0f;  // trunc entries are 0 or value

    __shared__ float sm[K2];
    sm[o] = cand;
    __syncthreads();
    for (int s = K2 / 2; s > 0; s >>= 1) {
        if (o < s) sm[o] = fmaxf(sm[o], sm[o + s]);
        __syncthreads();
    }
    const float voff = sm[0] * (float)T_DIM;       // v = trunc.max() * n_t
    __syncthreads();

    __shared__ float tots[K2];
    __shared__ unsigned long long pk[K2];
    __shared__ unsigned char sel[K2];
    tots[o] = (cnt > 0) ? (float)cnt * (value + voff) : 0.0f;
    sel[o]  = 0;
    __syncthreads();

    // 8 rounds: argmax (first index on ties), mark if nonzero, zero winner
    for (int r = 0; r < 8; r++) {
        // totals >= 0 so float bits are order-preserving as uint
        pk[o] = ((unsigned long long)__float_as_uint(tots[o]) << 32)
                | (unsigned)(K2 - 1 - o);          // smaller idx wins ties
        __syncthreads();
        for (int s = K2 / 2; s > 0; s >>= 1) {
            if (o < s) { unsigned long long b = pk[o + s]; if (b > pk[o]) pk[o] = b; }
            __syncthreads();
        }
        if (o == 0) {
            const int idx = (K2 - 1) - (int)(unsigned)(pk[0] & 0xffffffffULL);
            if (tots[idx] != 0.0f) sel[idx] = 1;
            tots[idx] = 0.0f;
        }
        __syncthreads();
    }

#pragma unroll
    for (int t = 0; t < T_DIM; t++) {
        outp[t * K2 + o] = (sel[o] && ((mask >> t) & 1u)) ? 1.0f : 0.0f;
    }
}

// ---------------------------------------------------------------------------
extern "C" void kernel_launch(void* const* d_in, const int* in_sizes, int n_in,
                              void* d_out, int out_size)
{
    const float* rec = (const float*)d_in[0];   // (32,1,64,4096)
    const float* wgt = (const float*)d_in[1];   // (512,1,64,4096)
    // defensive: identify by size (rec is the small one)
    if (n_in >= 2 && in_sizes[0] > in_sizes[1]) {
        const float* tmp = rec; rec = wgt; wgt = tmp;
    }
    float* outp = (float*)d_out;

    gemm_kernel<<<dim3(2, NSPLIT), 128>>>(rec, wgt);
    reduce_kernel<<<K2, 256>>>();
    post_kernel<<<1, K2>>>(outp);
}